// round 6
// baseline (speedup 1.0000x reference)
#include <cuda_runtime.h>
#include <cuda_bf16.h>
#include <cstdint>

// ---------------------------------------------------------------- constants
constexpr int MTOK = 8192, DIN = 4096, DOUT = 4096;
constexpr int E = 8, DK = 32, R = 16;
constexpr int NPROJ = 640, NPROJ_PAD = 768;
constexpr int KBASE = 3 * DIN;            // 12288 (hi|lo|hi split panels)
constexpr int GCOLS = 160;                // 128 lora + 1 bias + 31 pad
constexpr int KEXT  = 512;                // 3*160 + 32 pad
constexpr int KP    = KBASE + KEXT;       // 12800

// GEMM tiling (cg2 pair computes 256x256 tile)
constexpr int TM = 256, TN = 256, BK = 64, NST = 4;
constexpr int STAGE_BYTES = 2 * 128 * 128;           // A 16KB + B 16KB
constexpr int SMEM_DATA0  = 1024;
constexpr int SMEM_BYTES  = SMEM_DATA0 + NST * STAGE_BYTES;   // 132096
constexpr uint32_t IDESC = (1u<<4) | (1u<<7) | (1u<<10) | ((TN/8)<<17) | ((TM/16)<<24);

// ---------------------------------------------------------------- scratch
__device__ __align__(1024) __nv_bfloat16 g_Xp[(size_t)MTOK * KP];
__device__ __align__(1024) __nv_bfloat16 g_Wp[(size_t)DOUT * KP];
__device__ __align__(1024) __nv_bfloat16 g_Pp[(size_t)NPROJ_PAD * DIN];
__device__ __align__(1024) float         g_P [(size_t)MTOK * NPROJ_PAD];

// ---------------------------------------------------------------- ptx utils
__device__ __forceinline__ uint32_t smem_u32(const void* p) {
    uint32_t a;
    asm("{ .reg .u64 t; cvta.to.shared.u64 t, %1; cvt.u32.u64 %0, t; }" : "=r"(a) : "l"(p));
    return a;
}
__device__ __forceinline__ uint32_t ctarank() {
    uint32_t r; asm("mov.u32 %0, %%cluster_ctarank;" : "=r"(r)); return r;
}
__device__ __forceinline__ void cluster_sync() {
    asm volatile("barrier.cluster.arrive.aligned;" ::: "memory");
    asm volatile("barrier.cluster.wait.aligned;" ::: "memory");
}
__device__ __forceinline__ void mbar_init(uint32_t a, uint32_t c) {
    asm volatile("mbarrier.init.shared.b64 [%0], %1;" :: "r"(a), "r"(c) : "memory");
}
__device__ __forceinline__ void mbar_inval(uint32_t a) {
    asm volatile("mbarrier.inval.shared.b64 [%0];" :: "r"(a) : "memory");
}
__device__ __forceinline__ void mbar_arrive_rank0(uint32_t a) {
    asm volatile("{ .reg .b32 ra; mapa.shared::cluster.u32 ra, %0, 0;"
                 " mbarrier.arrive.shared::cluster.b64 _, [ra]; }" :: "r"(a) : "memory");
}
__device__ __forceinline__ void mbar_wait(uint32_t a, uint32_t parity) {
    asm volatile("{ .reg .pred P;\n"
                 "W%=: mbarrier.try_wait.parity.acquire.cta.shared::cta.b64 P, [%0], %1, 0x989680;\n"
                 "@P bra D%=;\n bra W%=;\nD%=: }"
                 :: "r"(a), "r"(parity) : "memory");
}
__device__ __forceinline__ void cpa16(uint32_t s, const void* g) {
    asm volatile("cp.async.cg.shared.global [%0], [%1], 16;" :: "r"(s), "l"(g));
}
__device__ __forceinline__ void cp_commit() { asm volatile("cp.async.commit_group;"); }
template <int N> __device__ __forceinline__ void cp_wait() {
    asm volatile("cp.async.wait_group %0;" :: "n"(N));
}
__device__ __forceinline__ void fence_async() {
    asm volatile("fence.proxy.async.shared::cta;" ::: "memory");
}
// SW128 K-major descriptor (LBO=1, SBO=64), Blackwell version bit
constexpr uint64_t DESC_BASE = (2ull<<61) | (1ull<<46) | (64ull<<32) | (1ull<<16);
__device__ __forceinline__ uint64_t mk_desc(uint32_t a) { return DESC_BASE | ((a >> 4) & 0x3FFF); }

// ---------------------------------------------------------------- pack kernels
__device__ __forceinline__ void split2(float v, __nv_bfloat16& hi, __nv_bfloat16& lo) {
    hi = __float2bfloat16(v);
    lo = __float2bfloat16(v - __bfloat162float(hi));
}
__device__ __forceinline__ uint32_t pack2(__nv_bfloat16 a, __nv_bfloat16 b) {
    __nv_bfloat162 t(a, b);
    return *reinterpret_cast<uint32_t*>(&t);
}

// x -> [hi | lo | hi], 4 cols per thread, uint2 stores
__global__ void split_x_kernel(const float* __restrict__ x) {
    size_t t = (size_t)blockIdx.x * 256 + threadIdx.x;
    if (t >= (size_t)MTOK * DIN / 4) return;
    int row = (int)(t / (DIN / 4));
    int col = (int)(t % (DIN / 4)) * 4;
    float4 v = *reinterpret_cast<const float4*>(x + (size_t)row * DIN + col);
    __nv_bfloat16 h0,l0,h1,l1,h2,l2,h3,l3;
    split2(v.x,h0,l0); split2(v.y,h1,l1); split2(v.z,h2,l2); split2(v.w,h3,l3);
    uint2 hh = make_uint2(pack2(h0,h1), pack2(h2,h3));
    uint2 ll = make_uint2(pack2(l0,l1), pack2(l2,l3));
    __nv_bfloat16* d = g_Xp + (size_t)row * KP;
    *reinterpret_cast<uint2*>(d + col)            = hh;
    *reinterpret_cast<uint2*>(d + DIN + col)      = ll;
    *reinterpret_cast<uint2*>(d + 2 * DIN + col)  = hh;
}

// W -> [hi | hi | lo]
__global__ void split_w_kernel(const float* __restrict__ W) {
    size_t t = (size_t)blockIdx.x * 256 + threadIdx.x;
    if (t >= (size_t)DOUT * DIN / 4) return;
    int row = (int)(t / (DIN / 4));
    int col = (int)(t % (DIN / 4)) * 4;
    float4 v = *reinterpret_cast<const float4*>(W + (size_t)row * DIN + col);
    __nv_bfloat16 h0,l0,h1,l1,h2,l2,h3,l3;
    split2(v.x,h0,l0); split2(v.y,h1,l1); split2(v.z,h2,l2); split2(v.w,h3,l3);
    uint2 hh = make_uint2(pack2(h0,h1), pack2(h2,h3));
    uint2 ll = make_uint2(pack2(l0,l1), pack2(l2,l3));
    __nv_bfloat16* d = g_Wp + (size_t)row * KP;
    *reinterpret_cast<uint2*>(d + col)            = hh;
    *reinterpret_cast<uint2*>(d + DIN + col)      = hh;
    *reinterpret_cast<uint2*>(d + 2 * DIN + col)  = ll;
}

__global__ void split_proj_kernel(const float* __restrict__ Wq,
                                  const float* __restrict__ Wk,
                                  const float* __restrict__ A) {
    size_t t = (size_t)blockIdx.x * 256 + threadIdx.x;
    if (t >= (size_t)NPROJ_PAD * DIN / 4) return;
    int row = (int)(t / (DIN / 4));
    int col = (int)(t % (DIN / 4)) * 4;
    float4 v = make_float4(0.f, 0.f, 0.f, 0.f);
    if (row < 256)      v = *reinterpret_cast<const float4*>(Wq + (size_t)row * DIN + col);
    else if (row < 512) v = *reinterpret_cast<const float4*>(Wk + (size_t)(row - 256) * DIN + col);
    else if (row < 640) v = *reinterpret_cast<const float4*>(A  + (size_t)(row - 512) * DIN + col);
    uint2 hh = make_uint2(pack2(__float2bfloat16(v.x), __float2bfloat16(v.y)),
                          pack2(__float2bfloat16(v.z), __float2bfloat16(v.w)));
    *reinterpret_cast<uint2*>(g_Pp + (size_t)row * DIN + col) = hh;
}

__global__ void pack_b2_kernel(const float* __restrict__ Bm, const float* __restrict__ b) {
    int idx = blockIdx.x * 256 + threadIdx.x;
    if (idx >= DOUT * KEXT) return;
    int o = idx / KEXT, jj = idx - o * KEXT;
    int jb = (jj < GCOLS) ? jj : (jj < 2*GCOLS) ? jj - GCOLS : (jj < 3*GCOLS) ? jj - 2*GCOLS : -1;
    float v = 0.f;
    if (jb >= 0) {
        if (jb < E * R) { int e = jb >> 4, r = jb & 15; v = Bm[((size_t)e * DOUT + o) * R + r]; }
        else if (jb == E * R) v = b[o];
    }
    __nv_bfloat16 hi, lo; split2(v, hi, lo);
    __nv_bfloat16 outv = (jj < 2*GCOLS) ? hi : (jj < 3*GCOLS) ? lo : __float2bfloat16(0.f);
    g_Wp[(size_t)o * KP + KBASE + jj] = outv;
}

// ---------------------------------------------------------------- routing
__global__ void routing_kernel() {
    int warp = (blockIdx.x * blockDim.x + threadIdx.x) >> 5;
    int lane = threadIdx.x & 31;
    if (warp >= MTOK) return;
    const float* Pt = g_P + (size_t)warp * NPROJ_PAD;
    float s[E];
#pragma unroll
    for (int e = 0; e < E; e++) {
        float p = Pt[e * DK + lane] * Pt[E * DK + e * DK + lane];
#pragma unroll
        for (int o = 16; o > 0; o >>= 1) p += __shfl_xor_sync(0xffffffffu, p, o);
        s[e] = p * 0.17677669529663687f;
    }
    float m = s[0];
#pragma unroll
    for (int e = 1; e < E; e++) m = fmaxf(m, s[e]);
    float Z = 0.f;
#pragma unroll
    for (int e = 0; e < E; e++) { s[e] = __expf(s[e] - m); Z += s[e]; }
    float inv = 1.f / Z;

    __nv_bfloat16* Gt = g_Xp + (size_t)warp * KP + KBASE;
#pragma unroll
    for (int j = lane; j < KEXT; j += 32) {
        int jb = (j < GCOLS) ? j : (j < 2*GCOLS) ? j - GCOLS : (j < 3*GCOLS) ? j - 2*GCOLS : -1;
        float g = 0.f;
        if (jb >= 0) {
            if (jb < E * R)       g = s[jb >> 4] * inv * Pt[2 * E * DK + jb];
            else if (jb == E * R) g = 1.0f;
        }
        __nv_bfloat16 hi, lo; split2(g, hi, lo);
        Gt[j] = (j < GCOLS) ? hi : (j < 2*GCOLS) ? lo : (j < 3*GCOLS) ? hi : __float2bfloat16(0.f);
    }
}

// ---------------------------------------------------------------- tcgen05 GEMM
// Warp-specialized: warps 4..7 = producers, rank0/tid0 = MMA issue thread.
// Completion signaled by a dedicated single-phase DONE mbarrier (extra
// multicast commit) — parity-safe for threads that skipped the mainloop.
// MODE 0: A=g_Xp (lda KP), B=g_Pp (ld DIN), C=g_P (ld 768), K=DIN
// MODE 1: A=g_Xp (lda KP), B=g_Wp (ld KP),  C=out (ld DOUT), K=KP
template <int MODE>
__global__ void __cluster_dims__(2, 1, 1) __launch_bounds__(256, 1)
gemm_cg2_kernel(float* __restrict__ Cparam) {
#if defined(__CUDA_ARCH_FEAT_SM103_ALL)
    constexpr int LDA = KP;
    constexpr int LDB = (MODE == 0) ? DIN : KP;
    constexpr int LDC = (MODE == 0) ? NPROJ_PAD : DOUT;
    constexpr int NCH = ((MODE == 0) ? DIN : KP) / BK;

    const __nv_bfloat16* __restrict__ Ag = g_Xp;
    const __nv_bfloat16* __restrict__ Bg = (MODE == 0) ? g_Pp : g_Wp;
    float* __restrict__ Cg = (MODE == 0) ? g_P : Cparam;

    extern __shared__ char smem[];
    const uint32_t sbase = smem_u32(smem);
    const int tid = threadIdx.x, wid = tid >> 5, lane = tid & 31;
    const uint32_t rank = ctarank();
    const int n_tile = blockIdx.x >> 1;
    const int m_tile = blockIdx.y;

    const uint32_t FULL0 = sbase + 8;    // NST x 8B on rank0, count=256
    const uint32_t MMAB0 = sbase + 40;   // NST x 8B, count=1 (multicast commit)
    const uint32_t DONE  = sbase + 72;   // single-phase completion barrier

    if (tid == 0) {
#pragma unroll
        for (int s = 0; s < NST; s++) { mbar_init(FULL0 + s * 8, 256); mbar_init(MMAB0 + s * 8, 1); }
        mbar_init(DONE, 1);
    }
    if (wid == 0)
        asm volatile("tcgen05.alloc.cta_group::2.sync.aligned.shared::cta.b32 [%0], %1;"
                     :: "r"(sbase), "r"(512) : "memory");
    __syncthreads();
    uint32_t tmem;
    asm volatile("ld.shared.b32 %0, [%1];" : "=r"(tmem) : "r"(sbase));
    cluster_sync();   // mbarriers visible cluster-wide before any arrive/commit

    const __nv_bfloat16* Arow = Ag + (size_t)(m_tile * TM + rank * 128) * LDA;
    const __nv_bfloat16* Brow = Bg + (size_t)(n_tile * TN + rank * 128) * LDB;

    const bool is_prod = (wid >= 4);
    const int  ptid = tid - 128;   // 0..127 for producers

    if (is_prod) {
        // producer: 16 x 16B per chunk (8 for A-half, 8 for B-half)
        auto fill = [&](int chunk) {
            const int kb = chunk * BK;
            const uint32_t sa = sbase + SMEM_DATA0 + (chunk & (NST - 1)) * STAGE_BYTES;
            const uint32_t sb = sa + 16384;
#pragma unroll
            for (int p = 0; p < 8; p++) {
                int q = p * 128 + ptid;        // 0..1023
                int r = q >> 3, c = q & 7;
                uint32_t off = (uint32_t)(r * 128 + c * 16);
                uint32_t sw = off ^ ((off >> 3) & 0x70);
                cpa16(sa + sw, Arow + (size_t)r * LDA + kb + c * 8);
                cpa16(sb + sw, Brow + (size_t)r * LDB + kb + c * 8);
            }
            cp_commit();
        };

        uint32_t mph[NST] = {0, 0, 0, 0};
        fill(0); fill(1); fill(2);            // prefetch NST-1 stages
        for (int i = 0; i < NCH; i++) {
            const int j = i + NST - 1;
            if (j < NCH) {
                const int s2 = j & (NST - 1);
                if (j >= NST) { mbar_wait(MMAB0 + s2 * 8, mph[s2]); mph[s2] ^= 1; }
                fill(j);
            }
            const int rem = NCH - 1 - i;
            if (rem >= 2) cp_wait<2>(); else if (rem == 1) cp_wait<1>(); else cp_wait<0>();
            fence_async();                     // publish own writes to async proxy
            mbar_arrive_rank0(FULL0 + (i & (NST - 1)) * 8);
        }
    } else if (rank == 0 && tid == 0) {
        // MMA issue thread
        uint32_t fph[NST] = {0, 0, 0, 0};
        for (int i = 0; i < NCH; i++) {
            const int s = i & (NST - 1);
            mbar_wait(FULL0 + s * 8, fph[s]); fph[s] ^= 1;
            uint64_t ad = mk_desc(sbase + SMEM_DATA0 + s * STAGE_BYTES);
            uint64_t bd = mk_desc(sbase + SMEM_DATA0 + s * STAGE_BYTES + 16384);
#pragma unroll
            for (int kk = 0; kk < 4; kk++) {
                uint32_t en = ((i > 0) || (kk > 0)) ? 1u : 0u;
                uint64_t adk = ad + kk * 2, bdk = bd + kk * 2;
                asm volatile("{ .reg .pred p; setp.ne.u32 p, %5, 0;\n"
                             "tcgen05.mma.cta_group::2.kind::f16 [%0], %1, %2, %3,"
                             " {%4,%4,%4,%4,%4,%4,%4,%4}, p; }"
                             :: "r"(tmem), "l"(adk), "l"(bdk), "r"(IDESC), "r"(0u), "r"(en)
                             : "memory");
            }
            asm volatile("tcgen05.commit.cta_group::2.mbarrier::arrive::one.shared::cluster.multicast::cluster.b64 [%0], %1;"
                         :: "r"(MMAB0 + s * 8), "h"((uint16_t)3) : "memory");
        }
        // final completion signal on the single-phase DONE barrier (both CTAs)
        asm volatile("tcgen05.commit.cta_group::2.mbarrier::arrive::one.shared::cluster.multicast::cluster.b64 [%0], %1;"
                     :: "r"(DONE), "h"((uint16_t)3) : "memory");
    }

    // all threads: wait the single-phase DONE barrier (parity 0, unambiguous)
    mbar_wait(DONE, 0);
    asm volatile("tcgen05.fence::after_thread_sync;" ::: "memory");

    // epilogue: warp w -> rows (w&3)*32+lane, col half (w>>2)*128
    {
        const int gm = m_tile * TM + (int)rank * 128 + (wid & 3) * 32 + lane;
        float* crow = Cg + (size_t)gm * LDC + n_tile * TN + (wid >> 2) * 128;
        const uint32_t cbase0 = tmem + (uint32_t)((wid >> 2) * 128);
#pragma unroll
        for (int cb = 0; cb < 128; cb += 32) {
            uint32_t d[32];
            asm volatile("tcgen05.ld.sync.aligned.32x32b.x32.b32 "
                "{%0,%1,%2,%3,%4,%5,%6,%7,%8,%9,%10,%11,%12,%13,%14,%15,"
                "%16,%17,%18,%19,%20,%21,%22,%23,%24,%25,%26,%27,%28,%29,%30,%31}, [%32];"
                : "=r"(d[0]),"=r"(d[1]),"=r"(d[2]),"=r"(d[3]),"=r"(d[4]),"=r"(d[5]),"=r"(d[6]),"=r"(d[7]),
                  "=r"(d[8]),"=r"(d[9]),"=r"(d[10]),"=r"(d[11]),"=r"(d[12]),"=r"(d[13]),"=r"(d[14]),"=r"(d[15]),
                  "=r"(d[16]),"=r"(d[17]),"=r"(d[18]),"=r"(d[19]),"=r"(d[20]),"=r"(d[21]),"=r"(d[22]),"=r"(d[23]),
                  "=r"(d[24]),"=r"(d[25]),"=r"(d[26]),"=r"(d[27]),"=r"(d[28]),"=r"(d[29]),"=r"(d[30]),"=r"(d[31])
                : "r"(cbase0 + cb));
            asm volatile("tcgen05.wait::ld.sync.aligned;" ::: "memory");
#pragma unroll
            for (int c = 0; c < 32; c += 4) {
                float4 v = make_float4(__uint_as_float(d[c]), __uint_as_float(d[c + 1]),
                                       __uint_as_float(d[c + 2]), __uint_as_float(d[c + 3]));
                *reinterpret_cast<float4*>(crow + cb + c) = v;
            }
        }
    }

    __syncthreads();
    if (tid == 0) {
#pragma unroll
        for (int s = 0; s < NST; s++) { mbar_inval(FULL0 + s * 8); mbar_inval(MMAB0 + s * 8); }
        mbar_inval(DONE);
    }
    __syncthreads();
    if (wid == 0) {
        asm volatile("tcgen05.relinquish_alloc_permit.cta_group::2.sync.aligned;");
        asm volatile("tcgen05.dealloc.cta_group::2.sync.aligned.b32 %0, %1;" :: "r"(tmem), "r"(512));
    }
    cluster_sync();
#endif  // __CUDA_ARCH_FEAT_SM103_ALL
}

// ---------------------------------------------------------------- launch
// Inputs (metadata order): x, W, b, Wq, Wk, A, Bm
extern "C" void kernel_launch(void* const* d_in, const int* in_sizes, int n_in,
                              void* d_out, int out_size) {
    const float* x  = (const float*)d_in[0];
    const float* W  = (const float*)d_in[1];
    const float* b  = (const float*)d_in[2];
    const float* Wq = (const float*)d_in[3];
    const float* Wk = (const float*)d_in[4];
    const float* A  = (const float*)d_in[5];
    const float* Bm = (const float*)d_in[6];
    float* out = (float*)d_out;

    cudaFuncSetAttribute(gemm_cg2_kernel<0>, cudaFuncAttributeMaxDynamicSharedMemorySize, SMEM_BYTES);
    cudaFuncSetAttribute(gemm_cg2_kernel<1>, cudaFuncAttributeMaxDynamicSharedMemorySize, SMEM_BYTES);

    split_x_kernel   <<<(int)(((size_t)MTOK * DIN / 4 + 255) / 256), 256>>>(x);
    split_w_kernel   <<<(int)(((size_t)DOUT * DIN / 4 + 255) / 256), 256>>>(W);
    split_proj_kernel<<<(int)(((size_t)NPROJ_PAD * DIN / 4 + 255) / 256), 256>>>(Wq, Wk, A);
    pack_b2_kernel   <<<(DOUT * KEXT + 255) / 256, 256>>>(Bm, b);

    // projections P = x_hi @ [Wq;Wk;A]_hi^T  (single-panel bf16, K=4096)
    gemm_cg2_kernel<0><<<dim3(2 * (NPROJ_PAD / TN), MTOK / TM), 256, SMEM_BYTES>>>(nullptr);

    // routing -> G extension columns of Xp
    routing_kernel<<<(MTOK * 32) / 256, 256>>>();

    // out = x @ W^T + G @ B2^T (+bias): flat K = 12800 split-bf16 GEMM
    gemm_cg2_kernel<1><<<dim3(2 * (DOUT / TN), MTOK / TM), 256, SMEM_BYTES>>>(out);
}

// round 7
// speedup vs baseline: 1.5786x; 1.5786x over previous
#include <cuda_runtime.h>
#include <cuda_bf16.h>
#include <cstdint>

// ---------------------------------------------------------------- constants
constexpr int MTOK = 8192, DIN = 4096, DOUT = 4096;
constexpr int E = 8, DK = 32, R = 16;
constexpr int NPROJ = 640, NPROJ_PAD = 768;
constexpr int KBASE = 3 * DIN;            // 12288 (hi|lo|hi split panels)
constexpr int GCOLS = 160;                // 128 lora + 1 bias + 31 pad
constexpr int KEXT  = 512;                // 3*160 + 32 pad
constexpr int KP    = KBASE + KEXT;       // 12800

constexpr int BK = 64, NST = 4;
constexpr int SMEM_DATA0 = 1024;
constexpr uint32_t IDESC = (1u<<4) | (1u<<7) | (1u<<10) | ((256/8)<<17) | ((256/16)<<24);

// ---------------------------------------------------------------- scratch
__device__ __align__(1024) __nv_bfloat16 g_Xp[(size_t)MTOK * KP];
__device__ __align__(1024) __nv_bfloat16 g_Wp[(size_t)DOUT * KP];
__device__ __align__(1024) __nv_bfloat16 g_Pp[(size_t)NPROJ_PAD * DIN];
__device__ __align__(1024) float         g_P [(size_t)MTOK * NPROJ_PAD];

// ---------------------------------------------------------------- ptx utils
__device__ __forceinline__ uint32_t smem_u32(const void* p) {
    uint32_t a;
    asm("{ .reg .u64 t; cvta.to.shared.u64 t, %1; cvt.u32.u64 %0, t; }" : "=r"(a) : "l"(p));
    return a;
}
__device__ __forceinline__ uint32_t ctarank() {
    uint32_t r; asm("mov.u32 %0, %%cluster_ctarank;" : "=r"(r)); return r;
}
__device__ __forceinline__ void cluster_sync() {
    asm volatile("barrier.cluster.arrive.aligned;" ::: "memory");
    asm volatile("barrier.cluster.wait.aligned;" ::: "memory");
}
__device__ __forceinline__ void mbar_init(uint32_t a, uint32_t c) {
    asm volatile("mbarrier.init.shared.b64 [%0], %1;" :: "r"(a), "r"(c) : "memory");
}
__device__ __forceinline__ void mbar_inval(uint32_t a) {
    asm volatile("mbarrier.inval.shared.b64 [%0];" :: "r"(a) : "memory");
}
__device__ __forceinline__ void mbar_arrive_rank0(uint32_t a) {
    asm volatile("{ .reg .b32 ra; mapa.shared::cluster.u32 ra, %0, 0;"
                 " mbarrier.arrive.shared::cluster.b64 _, [ra]; }" :: "r"(a) : "memory");
}
__device__ __forceinline__ void mbar_wait(uint32_t a, uint32_t parity) {
    asm volatile("{ .reg .pred P;\n"
                 "W%=: mbarrier.try_wait.parity.acquire.cta.shared::cta.b64 P, [%0], %1, 0x989680;\n"
                 "@P bra D%=;\n bra W%=;\nD%=: }"
                 :: "r"(a), "r"(parity) : "memory");
}
__device__ __forceinline__ void cpa16(uint32_t s, const void* g) {
    asm volatile("cp.async.cg.shared.global [%0], [%1], 16;" :: "r"(s), "l"(g));
}
__device__ __forceinline__ void cp_commit() { asm volatile("cp.async.commit_group;"); }
template <int N> __device__ __forceinline__ void cp_wait() {
    asm volatile("cp.async.wait_group %0;" :: "n"(N));
}
__device__ __forceinline__ void fence_async() {
    asm volatile("fence.proxy.async.shared::cta;" ::: "memory");
}
// SW128 K-major descriptor (LBO=1, SBO=64), Blackwell version bit
constexpr uint64_t DESC_BASE = (2ull<<61) | (1ull<<46) | (64ull<<32) | (1ull<<16);
__device__ __forceinline__ uint64_t mk_desc(uint32_t a) { return DESC_BASE | ((a >> 4) & 0x3FFF); }

// ---------------------------------------------------------------- pack kernels
__device__ __forceinline__ void split2(float v, __nv_bfloat16& hi, __nv_bfloat16& lo) {
    hi = __float2bfloat16(v);
    lo = __float2bfloat16(v - __bfloat162float(hi));
}
__device__ __forceinline__ uint32_t pack2(__nv_bfloat16 a, __nv_bfloat16 b) {
    __nv_bfloat162 t(a, b);
    return *reinterpret_cast<uint32_t*>(&t);
}

__global__ void split_x_kernel(const float* __restrict__ x) {
    size_t t = (size_t)blockIdx.x * 256 + threadIdx.x;
    if (t >= (size_t)MTOK * DIN / 4) return;
    int row = (int)(t / (DIN / 4));
    int col = (int)(t % (DIN / 4)) * 4;
    float4 v = *reinterpret_cast<const float4*>(x + (size_t)row * DIN + col);
    __nv_bfloat16 h0,l0,h1,l1,h2,l2,h3,l3;
    split2(v.x,h0,l0); split2(v.y,h1,l1); split2(v.z,h2,l2); split2(v.w,h3,l3);
    uint2 hh = make_uint2(pack2(h0,h1), pack2(h2,h3));
    uint2 ll = make_uint2(pack2(l0,l1), pack2(l2,l3));
    __nv_bfloat16* d = g_Xp + (size_t)row * KP;
    *reinterpret_cast<uint2*>(d + col)            = hh;
    *reinterpret_cast<uint2*>(d + DIN + col)      = ll;
    *reinterpret_cast<uint2*>(d + 2 * DIN + col)  = hh;
}

__global__ void split_w_kernel(const float* __restrict__ W) {
    size_t t = (size_t)blockIdx.x * 256 + threadIdx.x;
    if (t >= (size_t)DOUT * DIN / 4) return;
    int row = (int)(t / (DIN / 4));
    int col = (int)(t % (DIN / 4)) * 4;
    float4 v = *reinterpret_cast<const float4*>(W + (size_t)row * DIN + col);
    __nv_bfloat16 h0,l0,h1,l1,h2,l2,h3,l3;
    split2(v.x,h0,l0); split2(v.y,h1,l1); split2(v.z,h2,l2); split2(v.w,h3,l3);
    uint2 hh = make_uint2(pack2(h0,h1), pack2(h2,h3));
    uint2 ll = make_uint2(pack2(l0,l1), pack2(l2,l3));
    __nv_bfloat16* d = g_Wp + (size_t)row * KP;
    *reinterpret_cast<uint2*>(d + col)            = hh;
    *reinterpret_cast<uint2*>(d + DIN + col)      = hh;
    *reinterpret_cast<uint2*>(d + 2 * DIN + col)  = ll;
}

__global__ void split_proj_kernel(const float* __restrict__ Wq,
                                  const float* __restrict__ Wk,
                                  const float* __restrict__ A) {
    size_t t = (size_t)blockIdx.x * 256 + threadIdx.x;
    if (t >= (size_t)NPROJ_PAD * DIN / 4) return;
    int row = (int)(t / (DIN / 4));
    int col = (int)(t % (DIN / 4)) * 4;
    float4 v = make_float4(0.f, 0.f, 0.f, 0.f);
    if (row < 256)      v = *reinterpret_cast<const float4*>(Wq + (size_t)row * DIN + col);
    else if (row < 512) v = *reinterpret_cast<const float4*>(Wk + (size_t)(row - 256) * DIN + col);
    else if (row < 640) v = *reinterpret_cast<const float4*>(A  + (size_t)(row - 512) * DIN + col);
    uint2 hh = make_uint2(pack2(__float2bfloat16(v.x), __float2bfloat16(v.y)),
                          pack2(__float2bfloat16(v.z), __float2bfloat16(v.w)));
    *reinterpret_cast<uint2*>(g_Pp + (size_t)row * DIN + col) = hh;
}

__global__ void pack_b2_kernel(const float* __restrict__ Bm, const float* __restrict__ b) {
    int idx = blockIdx.x * 256 + threadIdx.x;
    if (idx >= DOUT * KEXT) return;
    int o = idx / KEXT, jj = idx - o * KEXT;
    int jb = (jj < GCOLS) ? jj : (jj < 2*GCOLS) ? jj - GCOLS : (jj < 3*GCOLS) ? jj - 2*GCOLS : -1;
    float v = 0.f;
    if (jb >= 0) {
        if (jb < E * R) { int e = jb >> 4, r = jb & 15; v = Bm[((size_t)e * DOUT + o) * R + r]; }
        else if (jb == E * R) v = b[o];
    }
    __nv_bfloat16 hi, lo; split2(v, hi, lo);
    __nv_bfloat16 outv = (jj < 2*GCOLS) ? hi : (jj < 3*GCOLS) ? lo : __float2bfloat16(0.f);
    g_Wp[(size_t)o * KP + KBASE + jj] = outv;
}

// ---------------------------------------------------------------- routing
__global__ void routing_kernel() {
    int warp = (blockIdx.x * blockDim.x + threadIdx.x) >> 5;
    int lane = threadIdx.x & 31;
    if (warp >= MTOK) return;
    const float* Pt = g_P + (size_t)warp * NPROJ_PAD;
    float s[E];
#pragma unroll
    for (int e = 0; e < E; e++) {
        float p = Pt[e * DK + lane] * Pt[E * DK + e * DK + lane];
#pragma unroll
        for (int o = 16; o > 0; o >>= 1) p += __shfl_xor_sync(0xffffffffu, p, o);
        s[e] = p * 0.17677669529663687f;
    }
    float m = s[0];
#pragma unroll
    for (int e = 1; e < E; e++) m = fmaxf(m, s[e]);
    float Z = 0.f;
#pragma unroll
    for (int e = 0; e < E; e++) { s[e] = __expf(s[e] - m); Z += s[e]; }
    float inv = 1.f / Z;

    __nv_bfloat16* Gt = g_Xp + (size_t)warp * KP + KBASE;
#pragma unroll
    for (int j = lane; j < KEXT; j += 32) {
        int jb = (j < GCOLS) ? j : (j < 2*GCOLS) ? j - GCOLS : (j < 3*GCOLS) ? j - 2*GCOLS : -1;
        float g = 0.f;
        if (jb >= 0) {
            if (jb < E * R)       g = s[jb >> 4] * inv * Pt[2 * E * DK + jb];
            else if (jb == E * R) g = 1.0f;
        }
        __nv_bfloat16 hi, lo; split2(g, hi, lo);
        Gt[j] = (j < GCOLS) ? hi : (j < 2*GCOLS) ? lo : (j < 3*GCOLS) ? hi : __float2bfloat16(0.f);
    }
}

// ---------------------------------------------------------------- tcgen05 GEMM
// R4-proven lockstep pipeline; tile widened to TM=256 x TN=256*NH per cg2 pair.
// NH=2 for the main GEMM (D fills all 512 TMEM cols) -> LTS traffic 6.7->5.0 GB.
// MODE 0: NH=1, A=g_Xp, B=g_Pp (ld DIN),  C=g_P (ld 768), K=DIN
// MODE 1: NH=2, A=g_Xp, B=g_Wp (ld KP),   C=out (ld DOUT), K=KP
template <int MODE>
__global__ void __cluster_dims__(2, 1, 1) __launch_bounds__(256, 1)
gemm_cg2_kernel(float* __restrict__ Cparam) {
#if defined(__CUDA_ARCH_FEAT_SM103_ALL)
    constexpr int NH  = (MODE == 0) ? 1 : 2;          // N halves (256 cols each)
    constexpr int TNK = NH * 256;                     // pair tile N
    constexpr int LDA = KP;
    constexpr int LDB = (MODE == 0) ? DIN : KP;
    constexpr int LDC = (MODE == 0) ? NPROJ_PAD : DOUT;
    constexpr int NCH = ((MODE == 0) ? DIN : KP) / BK;
    constexpr int STAGE_BYTES = 16384 * (1 + NH);     // A 16KB + B NH*16KB
    constexpr int SLAST = (NCH - 1) & (NST - 1);
    constexpr uint32_t FINPAR = ((NCH / NST) - 1) & 1;
    constexpr int WCOLS = TNK / 2;                    // cols per warp group half

    const __nv_bfloat16* __restrict__ Ag = g_Xp;
    const __nv_bfloat16* __restrict__ Bg = (MODE == 0) ? g_Pp : g_Wp;
    float* __restrict__ Cg = (MODE == 0) ? g_P : Cparam;

    extern __shared__ char smem[];
    const uint32_t sbase = smem_u32(smem);
    const int tid = threadIdx.x, wid = tid >> 5, lane = tid & 31;
    const uint32_t rank = ctarank();
    const int n_tile = blockIdx.x >> 1;
    const int m_tile = blockIdx.y;

    const uint32_t FULL0 = sbase + 8;    // NST x 8B on rank0, count=2
    const uint32_t MMAB0 = sbase + 40;   // NST x 8B, count=1 (multicast commit)

    if (tid == 0) {
#pragma unroll
        for (int s = 0; s < NST; s++) { mbar_init(FULL0 + s * 8, 2); mbar_init(MMAB0 + s * 8, 1); }
    }
    if (wid == 0)
        asm volatile("tcgen05.alloc.cta_group::2.sync.aligned.shared::cta.b32 [%0], %1;"
                     :: "r"(sbase), "r"(512) : "memory");
    __syncthreads();
    uint32_t tmem;
    asm volatile("ld.shared.b32 %0, [%1];" : "=r"(tmem) : "r"(sbase));
    cluster_sync();   // mbarriers visible cluster-wide before any arrive/commit

    const __nv_bfloat16* Arow = Ag + (size_t)(m_tile * 256 + rank * 128) * LDA;
    const __nv_bfloat16* Brow = Bg + (size_t)(n_tile * TNK + rank * 128) * LDB;

    auto fill = [&](int chunk) {
        const int kb = chunk * BK;
        const uint32_t st = sbase + SMEM_DATA0 + (chunk & (NST - 1)) * STAGE_BYTES;
#pragma unroll
        for (int p = 0; p < 4; p++) {
            int q = p * 256 + tid;
            int r = q >> 3, c = q & 7;
            uint32_t off = (uint32_t)(r * 128 + c * 16);
            uint32_t sw = off ^ ((off >> 3) & 0x70);
            cpa16(st + sw, Arow + (size_t)r * LDA + kb + c * 8);
        }
#pragma unroll
        for (int h = 0; h < NH; h++) {
            const __nv_bfloat16* Bh = Brow + (size_t)(h * 256) * LDB;
            const uint32_t sb = st + 16384 + h * 16384;
#pragma unroll
            for (int p = 0; p < 4; p++) {
                int q = p * 256 + tid;
                int r = q >> 3, c = q & 7;
                uint32_t off = (uint32_t)(r * 128 + c * 16);
                uint32_t sw = off ^ ((off >> 3) & 0x70);
                cpa16(sb + sw, Bh + (size_t)r * LDB + kb + c * 8);
            }
        }
        cp_commit();
    };

    uint32_t fphase[NST] = {0, 0, 0, 0};
    uint32_t mphase[NST] = {0, 0, 0, 0};

    fill(0); fill(1); fill(2);

    for (int i = 0; i < NCH; i++) {
        const int s = i & (NST - 1);
        const int rem = NCH - 1 - i;
        if (rem >= 2) cp_wait<2>(); else if (rem == 1) cp_wait<1>(); else cp_wait<0>();
        __syncthreads();
        if (tid == 0) {
            fence_async();
            mbar_arrive_rank0(FULL0 + s * 8);
        }
        if (rank == 0 && tid == 0) {
            mbar_wait(FULL0 + s * 8, fphase[s]); fphase[s] ^= 1;
            const uint32_t st = sbase + SMEM_DATA0 + s * STAGE_BYTES;
            uint64_t ad = mk_desc(st);
#pragma unroll
            for (int h = 0; h < NH; h++) {
                uint64_t bd = mk_desc(st + 16384 + h * 16384);
#pragma unroll
                for (int kk = 0; kk < 4; kk++) {
                    uint32_t en = ((i > 0) || (kk > 0)) ? 1u : 0u;
                    uint64_t adk = ad + kk * 2, bdk = bd + kk * 2;
                    uint32_t dh = tmem + h * 256;
                    asm volatile("{ .reg .pred p; setp.ne.u32 p, %5, 0;\n"
                                 "tcgen05.mma.cta_group::2.kind::f16 [%0], %1, %2, %3,"
                                 " {%4,%4,%4,%4,%4,%4,%4,%4}, p; }"
                                 :: "r"(dh), "l"(adk), "l"(bdk), "r"(IDESC), "r"(0u), "r"(en)
                                 : "memory");
                }
            }
            asm volatile("tcgen05.commit.cta_group::2.mbarrier::arrive::one.shared::cluster.multicast::cluster.b64 [%0], %1;"
                         :: "r"(MMAB0 + s * 8), "h"((uint16_t)3) : "memory");
        }
        const int j = i + NST - 1;
        if (j < NCH) {
            const int s2 = j & (NST - 1);
            if (j >= NST) { mbar_wait(MMAB0 + s2 * 8, mphase[s2]); mphase[s2] ^= 1; }
            fill(j);
        }
    }

    // wait final MMA (all threads tracked MMAB phases through the loop)
    mbar_wait(MMAB0 + SLAST * 8, FINPAR);
    asm volatile("tcgen05.fence::after_thread_sync;" ::: "memory");

    // epilogue: warp w -> rows (w&3)*32+lane, col half (w>>2)*WCOLS
    {
        const int gm = m_tile * 256 + (int)rank * 128 + (wid & 3) * 32 + lane;
        float* crow = Cg + (size_t)gm * LDC + n_tile * TNK + (wid >> 2) * WCOLS;
        const uint32_t cbase0 = tmem + (uint32_t)((wid >> 2) * WCOLS);
#pragma unroll
        for (int cb = 0; cb < WCOLS; cb += 32) {
            uint32_t d[32];
            asm volatile("tcgen05.ld.sync.aligned.32x32b.x32.b32 "
                "{%0,%1,%2,%3,%4,%5,%6,%7,%8,%9,%10,%11,%12,%13,%14,%15,"
                "%16,%17,%18,%19,%20,%21,%22,%23,%24,%25,%26,%27,%28,%29,%30,%31}, [%32];"
                : "=r"(d[0]),"=r"(d[1]),"=r"(d[2]),"=r"(d[3]),"=r"(d[4]),"=r"(d[5]),"=r"(d[6]),"=r"(d[7]),
                  "=r"(d[8]),"=r"(d[9]),"=r"(d[10]),"=r"(d[11]),"=r"(d[12]),"=r"(d[13]),"=r"(d[14]),"=r"(d[15]),
                  "=r"(d[16]),"=r"(d[17]),"=r"(d[18]),"=r"(d[19]),"=r"(d[20]),"=r"(d[21]),"=r"(d[22]),"=r"(d[23]),
                  "=r"(d[24]),"=r"(d[25]),"=r"(d[26]),"=r"(d[27]),"=r"(d[28]),"=r"(d[29]),"=r"(d[30]),"=r"(d[31])
                : "r"(cbase0 + cb));
            asm volatile("tcgen05.wait::ld.sync.aligned;" ::: "memory");
#pragma unroll
            for (int c = 0; c < 32; c += 4) {
                float4 v = make_float4(__uint_as_float(d[c]), __uint_as_float(d[c + 1]),
                                       __uint_as_float(d[c + 2]), __uint_as_float(d[c + 3]));
                *reinterpret_cast<float4*>(crow + cb + c) = v;
            }
        }
    }

    __syncthreads();
    if (tid == 0) {
#pragma unroll
        for (int s = 0; s < NST; s++) { mbar_inval(FULL0 + s * 8); mbar_inval(MMAB0 + s * 8); }
    }
    __syncthreads();
    if (wid == 0) {
        asm volatile("tcgen05.relinquish_alloc_permit.cta_group::2.sync.aligned;");
        asm volatile("tcgen05.dealloc.cta_group::2.sync.aligned.b32 %0, %1;" :: "r"(tmem), "r"(512));
    }
    cluster_sync();
#endif  // __CUDA_ARCH_FEAT_SM103_ALL
}

// ---------------------------------------------------------------- launch
// Inputs (metadata order): x, W, b, Wq, Wk, A, Bm
extern "C" void kernel_launch(void* const* d_in, const int* in_sizes, int n_in,
                              void* d_out, int out_size) {
    const float* x  = (const float*)d_in[0];
    const float* W  = (const float*)d_in[1];
    const float* b  = (const float*)d_in[2];
    const float* Wq = (const float*)d_in[3];
    const float* Wk = (const float*)d_in[4];
    const float* A  = (const float*)d_in[5];
    const float* Bm = (const float*)d_in[6];
    float* out = (float*)d_out;

    constexpr int SMEM0 = SMEM_DATA0 + NST * (16384 * 2);   // MODE0: 132096
    constexpr int SMEM1 = SMEM_DATA0 + NST * (16384 * 3);   // MODE1: 197632
    cudaFuncSetAttribute(gemm_cg2_kernel<0>, cudaFuncAttributeMaxDynamicSharedMemorySize, SMEM0);
    cudaFuncSetAttribute(gemm_cg2_kernel<1>, cudaFuncAttributeMaxDynamicSharedMemorySize, SMEM1);

    split_x_kernel   <<<(int)(((size_t)MTOK * DIN / 4 + 255) / 256), 256>>>(x);
    split_w_kernel   <<<(int)(((size_t)DOUT * DIN / 4 + 255) / 256), 256>>>(W);
    split_proj_kernel<<<(int)(((size_t)NPROJ_PAD * DIN / 4 + 255) / 256), 256>>>(Wq, Wk, A);
    pack_b2_kernel   <<<(DOUT * KEXT + 255) / 256, 256>>>(Bm, b);

    // projections P = x_hi @ [Wq;Wk;A]_hi^T  (single-panel bf16, K=4096, TN=256)
    gemm_cg2_kernel<0><<<dim3(2 * (NPROJ_PAD / 256), MTOK / 256), 256, SMEM0>>>(nullptr);

    // routing -> G extension columns of Xp
    routing_kernel<<<(MTOK * 32) / 256, 256>>>();

    // out = x @ W^T + G @ B2^T (+bias): flat K = 12800, TN=512 per cg2 pair
    gemm_cg2_kernel<1><<<dim3(2 * (DOUT / 512), MTOK / 256), 256, SMEM1>>>(out);
}

// round 9
// speedup vs baseline: 1.6868x; 1.0686x over previous
#include <cuda_runtime.h>
#include <cuda_bf16.h>
#include <cstdint>

// ---------------------------------------------------------------- constants
constexpr int MTOK = 8192, DIN = 4096, DOUT = 4096;
constexpr int E = 8, DK = 32, R = 16;
constexpr int NPROJ = 640, NPROJ_PAD = 768;
constexpr int GEXT  = 192;                 // 128 lora + 1 bias + 63 pad (per panel)
constexpr int KP2   = 2 * DIN + 2 * GEXT;  // 8576: [x_hi | x_lo | G_hi | G_lo]
constexpr int EXT0  = 2 * DIN;             // 8192: start of hi ext panel

// ---------------------------------------------------------------- scratch
__device__ __align__(1024) __nv_bfloat16 g_Xp[(size_t)MTOK * KP2];
__device__ __align__(1024) __nv_bfloat16 g_Wp[(size_t)DOUT * KP2];
__device__ __align__(1024) __nv_bfloat16 g_Pp[(size_t)NPROJ_PAD * DIN];
__device__ __align__(1024) float         g_P [(size_t)MTOK * NPROJ_PAD];

// ---------------------------------------------------------------- ptx utils
__device__ __forceinline__ uint32_t smem_u32(const void* p) {
    uint32_t a;
    asm("{ .reg .u64 t; cvta.to.shared.u64 t, %1; cvt.u32.u64 %0, t; }" : "=r"(a) : "l"(p));
    return a;
}
__device__ __forceinline__ uint32_t ctarank() {
    uint32_t r; asm("mov.u32 %0, %%cluster_ctarank;" : "=r"(r)); return r;
}
__device__ __forceinline__ void cluster_sync() {
    asm volatile("barrier.cluster.arrive.aligned;" ::: "memory");
    asm volatile("barrier.cluster.wait.aligned;" ::: "memory");
}
__device__ __forceinline__ void mbar_init(uint32_t a, uint32_t c) {
    asm volatile("mbarrier.init.shared.b64 [%0], %1;" :: "r"(a), "r"(c) : "memory");
}
__device__ __forceinline__ void mbar_inval(uint32_t a) {
    asm volatile("mbarrier.inval.shared.b64 [%0];" :: "r"(a) : "memory");
}
__device__ __forceinline__ void mbar_arrive_rank0(uint32_t a) {
    asm volatile("{ .reg .b32 ra; mapa.shared::cluster.u32 ra, %0, 0;"
                 " mbarrier.arrive.shared::cluster.b64 _, [ra]; }" :: "r"(a) : "memory");
}
__device__ __forceinline__ void mbar_wait(uint32_t a, uint32_t parity) {
    asm volatile("{ .reg .pred P;\n"
                 "W%=: mbarrier.try_wait.parity.acquire.cta.shared::cta.b64 P, [%0], %1, 0x989680;\n"
                 "@P bra D%=;\n bra W%=;\nD%=: }"
                 :: "r"(a), "r"(parity) : "memory");
}
__device__ __forceinline__ void cpa16(uint32_t s, const void* g) {
    asm volatile("cp.async.cg.shared.global [%0], [%1], 16;" :: "r"(s), "l"(g));
}
__device__ __forceinline__ void cp_commit() { asm volatile("cp.async.commit_group;"); }
template <int N> __device__ __forceinline__ void cp_wait() {
    asm volatile("cp.async.wait_group %0;" :: "n"(N));
}
__device__ __forceinline__ void fence_async() {
    asm volatile("fence.proxy.async.shared::cta;" ::: "memory");
}
constexpr uint64_t DESC_BASE = (2ull<<61) | (1ull<<46) | (64ull<<32) | (1ull<<16);
__device__ __forceinline__ uint64_t mk_desc(uint32_t a) { return DESC_BASE | ((a >> 4) & 0x3FFF); }
constexpr uint32_t IDESC = (1u<<4) | (1u<<7) | (1u<<10) | ((256/8)<<17) | ((256/16)<<24);

__device__ __forceinline__ void mma_cg2(uint32_t d, uint64_t ad, uint64_t bd, uint32_t en) {
    asm volatile("{ .reg .pred p; setp.ne.u32 p, %5, 0;\n"
                 "tcgen05.mma.cta_group::2.kind::f16 [%0], %1, %2, %3,"
                 " {%4,%4,%4,%4,%4,%4,%4,%4}, p; }"
                 :: "r"(d), "l"(ad), "l"(bd), "r"(IDESC), "r"(0u), "r"(en) : "memory");
}

// ---------------------------------------------------------------- pack kernels
__device__ __forceinline__ void split2(float v, __nv_bfloat16& hi, __nv_bfloat16& lo) {
    hi = __float2bfloat16(v);
    lo = __float2bfloat16(v - __bfloat162float(hi));
}
__device__ __forceinline__ uint32_t pack2(__nv_bfloat16 a, __nv_bfloat16 b) {
    __nv_bfloat162 t(a, b);
    return *reinterpret_cast<uint32_t*>(&t);
}

// src row-major [rows, DIN] -> dst rows of KP2 with [hi | lo] panels
__device__ __forceinline__ void split_row4(const float* src, __nv_bfloat16* dstrow, int col) {
    float4 v = *reinterpret_cast<const float4*>(src + col);
    __nv_bfloat16 h0,l0,h1,l1,h2,l2,h3,l3;
    split2(v.x,h0,l0); split2(v.y,h1,l1); split2(v.z,h2,l2); split2(v.w,h3,l3);
    *reinterpret_cast<uint2*>(dstrow + col)       = make_uint2(pack2(h0,h1), pack2(h2,h3));
    *reinterpret_cast<uint2*>(dstrow + DIN + col) = make_uint2(pack2(l0,l1), pack2(l2,l3));
}

__global__ void split_x_kernel(const float* __restrict__ x) {
    size_t t = (size_t)blockIdx.x * 256 + threadIdx.x;
    if (t >= (size_t)MTOK * DIN / 4) return;
    int row = (int)(t / (DIN / 4)), col = (int)(t % (DIN / 4)) * 4;
    split_row4(x + (size_t)row * DIN, g_Xp + (size_t)row * KP2, col);
}

__global__ void split_w_kernel(const float* __restrict__ W) {
    size_t t = (size_t)blockIdx.x * 256 + threadIdx.x;
    if (t >= (size_t)DOUT * DIN / 4) return;
    int row = (int)(t / (DIN / 4)), col = (int)(t % (DIN / 4)) * 4;
    split_row4(W + (size_t)row * DIN, g_Wp + (size_t)row * KP2, col);
}

__global__ void split_proj_kernel(const float* __restrict__ Wq,
                                  const float* __restrict__ Wk,
                                  const float* __restrict__ A) {
    size_t t = (size_t)blockIdx.x * 256 + threadIdx.x;
    if (t >= (size_t)NPROJ_PAD * DIN / 4) return;
    int row = (int)(t / (DIN / 4)), col = (int)(t % (DIN / 4)) * 4;
    float4 v = make_float4(0.f, 0.f, 0.f, 0.f);
    if (row < 256)      v = *reinterpret_cast<const float4*>(Wq + (size_t)row * DIN + col);
    else if (row < 512) v = *reinterpret_cast<const float4*>(Wk + (size_t)(row - 256) * DIN + col);
    else if (row < 640) v = *reinterpret_cast<const float4*>(A  + (size_t)(row - 512) * DIN + col);
    *reinterpret_cast<uint2*>(g_Pp + (size_t)row * DIN + col) =
        make_uint2(pack2(__float2bfloat16(v.x), __float2bfloat16(v.y)),
                   pack2(__float2bfloat16(v.z), __float2bfloat16(v.w)));
}

// B2 ext: g_Wp cols [8192,8384)=hi, [8384,8576)=lo.
// B2[o,j]: j<128 -> Bm[e=j/16, o, r=j%16]; j==128 -> b[o]; else 0.
__global__ void pack_b2_kernel(const float* __restrict__ Bm, const float* __restrict__ b) {
    int idx = blockIdx.x * 256 + threadIdx.x;
    if (idx >= DOUT * GEXT) return;
    int o = idx / GEXT, j = idx - o * GEXT;
    float v = 0.f;
    if (j < E * R) { int e = j >> 4, r = j & 15; v = Bm[((size_t)e * DOUT + o) * R + r]; }
    else if (j == E * R) v = b[o];
    __nv_bfloat16 hi, lo; split2(v, hi, lo);
    g_Wp[(size_t)o * KP2 + EXT0 + j] = hi;
    g_Wp[(size_t)o * KP2 + EXT0 + GEXT + j] = lo;
}

// ---------------------------------------------------------------- routing
__global__ void routing_kernel() {
    int warp = (blockIdx.x * blockDim.x + threadIdx.x) >> 5;
    int lane = threadIdx.x & 31;
    if (warp >= MTOK) return;
    const float* Pt = g_P + (size_t)warp * NPROJ_PAD;
    float s[E];
#pragma unroll
    for (int e = 0; e < E; e++) {
        float p = Pt[e * DK + lane] * Pt[E * DK + e * DK + lane];
#pragma unroll
        for (int o = 16; o > 0; o >>= 1) p += __shfl_xor_sync(0xffffffffu, p, o);
        s[e] = p * 0.17677669529663687f;
    }
    float m = s[0];
#pragma unroll
    for (int e = 1; e < E; e++) m = fmaxf(m, s[e]);
    float Z = 0.f;
#pragma unroll
    for (int e = 0; e < E; e++) { s[e] = __expf(s[e] - m); Z += s[e]; }
    float inv = 1.f / Z;

    __nv_bfloat16* Gt = g_Xp + (size_t)warp * KP2 + EXT0;
#pragma unroll
    for (int j = lane; j < GEXT; j += 32) {
        float g = 0.f;
        if (j < E * R)       g = s[j >> 4] * inv * Pt[2 * E * DK + j];
        else if (j == E * R) g = 1.0f;
        __nv_bfloat16 hi, lo; split2(g, hi, lo);
        Gt[j] = hi;
        Gt[GEXT + j] = lo;
    }
}

// ---------------------------------------------------------------- proj GEMM (R7-proven, NH=1)
__global__ void __cluster_dims__(2, 1, 1) __launch_bounds__(256, 1)
gemm_proj_kernel() {
#if defined(__CUDA_ARCH_FEAT_SM103_ALL)
    constexpr int NST = 4, NCH = DIN / 64, STAGE = 32768;
    constexpr int SLAST = (NCH - 1) & (NST - 1);
    constexpr uint32_t FINPAR = (((NCH - 1 - SLAST) / NST + 1) - 1) & 1;

    extern __shared__ char smem[];
    const uint32_t sbase = smem_u32(smem);
    const int tid = threadIdx.x, wid = tid >> 5, lane = tid & 31;
    const uint32_t rank = ctarank();
    const int n_tile = blockIdx.x >> 1, m_tile = blockIdx.y;
    const uint32_t FULL0 = sbase + 8, MMAB0 = sbase + 40;

    if (tid == 0)
        for (int s = 0; s < NST; s++) { mbar_init(FULL0 + s * 8, 2); mbar_init(MMAB0 + s * 8, 1); }
    if (wid == 0)
        asm volatile("tcgen05.alloc.cta_group::2.sync.aligned.shared::cta.b32 [%0], %1;"
                     :: "r"(sbase), "r"(512) : "memory");
    __syncthreads();
    uint32_t tmem;
    asm volatile("ld.shared.b32 %0, [%1];" : "=r"(tmem) : "r"(sbase));
    cluster_sync();

    const __nv_bfloat16* Arow = g_Xp + (size_t)(m_tile * 256 + rank * 128) * KP2;
    const __nv_bfloat16* Brow = g_Pp + (size_t)(n_tile * 256 + rank * 128) * DIN;

    auto fill = [&](int chunk) {
        const int kb = chunk * 64;
        const uint32_t st = sbase + 1024 + (chunk & (NST - 1)) * STAGE;
#pragma unroll
        for (int p = 0; p < 4; p++) {
            int q = p * 256 + tid, r = q >> 3, c = q & 7;
            uint32_t off = (uint32_t)(r * 128 + c * 16);
            uint32_t sw = off ^ ((off >> 3) & 0x70);
            cpa16(st + sw, Arow + (size_t)r * KP2 + kb + c * 8);
            cpa16(st + 16384 + sw, Brow + (size_t)r * DIN + kb + c * 8);
        }
        cp_commit();
    };

    uint32_t fph[NST] = {}, mph[NST] = {};
    fill(0); fill(1); fill(2);
    for (int i = 0; i < NCH; i++) {
        const int s = i & (NST - 1), rem = NCH - 1 - i;
        if (rem >= 2) cp_wait<2>(); else if (rem == 1) cp_wait<1>(); else cp_wait<0>();
        __syncthreads();
        if (tid == 0) { fence_async(); mbar_arrive_rank0(FULL0 + s * 8); }
        if (rank == 0 && tid == 0) {
            mbar_wait(FULL0 + s * 8, fph[s]); fph[s] ^= 1;
            const uint32_t st = sbase + 1024 + s * STAGE;
            uint64_t ad = mk_desc(st), bd = mk_desc(st + 16384);
#pragma unroll
            for (int kk = 0; kk < 4; kk++)
                mma_cg2(tmem, ad + kk * 2, bd + kk * 2, (i > 0) || (kk > 0));
            asm volatile("tcgen05.commit.cta_group::2.mbarrier::arrive::one.shared::cluster.multicast::cluster.b64 [%0], %1;"
                         :: "r"(MMAB0 + s * 8), "h"((uint16_t)3) : "memory");
        }
        const int j = i + NST - 1;
        if (j < NCH) {
            const int s2 = j & (NST - 1);
            if (j >= NST) { mbar_wait(MMAB0 + s2 * 8, mph[s2]); mph[s2] ^= 1; }
            fill(j);
        }
    }
    mbar_wait(MMAB0 + SLAST * 8, FINPAR);
    asm volatile("tcgen05.fence::after_thread_sync;" ::: "memory");

    {
        const int gm = m_tile * 256 + (int)rank * 128 + (wid & 3) * 32 + lane;
        float* crow = g_P + (size_t)gm * NPROJ_PAD + n_tile * 256 + (wid >> 2) * 128;
        const uint32_t cb0 = tmem + (uint32_t)((wid >> 2) * 128);
#pragma unroll
        for (int cb = 0; cb < 128; cb += 32) {
            uint32_t d[32];
            asm volatile("tcgen05.ld.sync.aligned.32x32b.x32.b32 "
                "{%0,%1,%2,%3,%4,%5,%6,%7,%8,%9,%10,%11,%12,%13,%14,%15,"
                "%16,%17,%18,%19,%20,%21,%22,%23,%24,%25,%26,%27,%28,%29,%30,%31}, [%32];"
                : "=r"(d[0]),"=r"(d[1]),"=r"(d[2]),"=r"(d[3]),"=r"(d[4]),"=r"(d[5]),"=r"(d[6]),"=r"(d[7]),
                  "=r"(d[8]),"=r"(d[9]),"=r"(d[10]),"=r"(d[11]),"=r"(d[12]),"=r"(d[13]),"=r"(d[14]),"=r"(d[15]),
                  "=r"(d[16]),"=r"(d[17]),"=r"(d[18]),"=r"(d[19]),"=r"(d[20]),"=r"(d[21]),"=r"(d[22]),"=r"(d[23]),
                  "=r"(d[24]),"=r"(d[25]),"=r"(d[26]),"=r"(d[27]),"=r"(d[28]),"=r"(d[29]),"=r"(d[30]),"=r"(d[31])
                : "r"(cb0 + cb));
            asm volatile("tcgen05.wait::ld.sync.aligned;" ::: "memory");
#pragma unroll
            for (int c = 0; c < 32; c += 4)
                *reinterpret_cast<float4*>(crow + cb + c) =
                    make_float4(__uint_as_float(d[c]), __uint_as_float(d[c+1]),
                                __uint_as_float(d[c+2]), __uint_as_float(d[c+3]));
        }
    }
    __syncthreads();
    if (tid == 0) {
        for (int s = 0; s < NST; s++) { mbar_inval(FULL0 + s * 8); mbar_inval(MMAB0 + s * 8); }
    }
    __syncthreads();
    if (wid == 0) {
        asm volatile("tcgen05.relinquish_alloc_permit.cta_group::2.sync.aligned;");
        asm volatile("tcgen05.dealloc.cta_group::2.sync.aligned.b32 %0, %1;" :: "r"(tmem), "r"(512));
    }
    cluster_sync();
#endif
}

// ---------------------------------------------------------------- main GEMM (dedup 3-product)
// Per chunk (64 original K cols): load A_hi,A_lo (16KB ea), B_hi,B_lo (32KB ea, NH=2).
// Issue hi*hi + lo*hi + hi*lo for each N-half. NST=2 double buffer, 96KB stages.
__global__ void __cluster_dims__(2, 1, 1) __launch_bounds__(256, 1)
gemm_main_kernel(float* __restrict__ Cg) {
#if defined(__CUDA_ARCH_FEAT_SM103_ALL)
    constexpr int NST = 2;
    constexpr int NCH = DIN / 64 + GEXT / 64;       // 64 + 3 = 67
    constexpr int STAGE = 98304;                    // A 32KB + B 64KB
    constexpr int A_HI = 0, A_LO = 16384, B_HI = 32768, B_LO = 65536;
    constexpr int SLAST = (NCH - 1) & (NST - 1);    // 0
    constexpr uint32_t FINPAR = (((NCH - 1 - SLAST) / NST + 1) - 1) & 1;  // 1

    extern __shared__ char smem[];
    const uint32_t sbase = smem_u32(smem);
    const int tid = threadIdx.x, wid = tid >> 5, lane = tid & 31;
    const uint32_t rank = ctarank();
    const int n_tile = blockIdx.x >> 1, m_tile = blockIdx.y;
    const uint32_t FULL0 = sbase + 8, MMAB0 = sbase + 40;

    if (tid == 0)
        for (int s = 0; s < NST; s++) { mbar_init(FULL0 + s * 8, 2); mbar_init(MMAB0 + s * 8, 1); }
    if (wid == 0)
        asm volatile("tcgen05.alloc.cta_group::2.sync.aligned.shared::cta.b32 [%0], %1;"
                     :: "r"(sbase), "r"(512) : "memory");
    __syncthreads();
    uint32_t tmem;
    asm volatile("ld.shared.b32 %0, [%1];" : "=r"(tmem) : "r"(sbase));
    cluster_sync();

    const __nv_bfloat16* Arow = g_Xp + (size_t)(m_tile * 256 + rank * 128) * KP2;
    const __nv_bfloat16* Brow = g_Wp + (size_t)(n_tile * 512 + rank * 128) * KP2;

    // load one 128x64 sub-tile (K-major, SW128) with 4 cp.async per thread
    auto load_tile = [&](uint32_t sdst, const __nv_bfloat16* gsrc) {
#pragma unroll
        for (int p = 0; p < 4; p++) {
            int q = p * 256 + tid, r = q >> 3, c = q & 7;
            uint32_t off = (uint32_t)(r * 128 + c * 16);
            uint32_t sw = off ^ ((off >> 3) & 0x70);
            cpa16(sdst + sw, gsrc + (size_t)r * KP2 + c * 8);
        }
    };

    auto fill = [&](int chunk) {
        const int khi = (chunk < 64) ? chunk * 64 : EXT0 + (chunk - 64) * 64;
        const int klo = khi + ((chunk < 64) ? DIN : GEXT);
        const uint32_t st = sbase + 1024 + (chunk & (NST - 1)) * STAGE;
        load_tile(st + A_HI, Arow + khi);
        load_tile(st + A_LO, Arow + klo);
#pragma unroll
        for (int h = 0; h < 2; h++) {
            const __nv_bfloat16* Bh = Brow + (size_t)(h * 256) * KP2;
            load_tile(st + B_HI + h * 16384, Bh + khi);
            load_tile(st + B_LO + h * 16384, Bh + klo);
        }
        cp_commit();
    };

    uint32_t fph[NST] = {}, mph[NST] = {};
    fill(0);
    for (int i = 0; i < NCH; i++) {
        const int s = i & (NST - 1);
        cp_wait<0>();          // NST=2: fill(i) must be complete (fill(i+1) not yet committed)
        __syncthreads();
        if (tid == 0) { fence_async(); mbar_arrive_rank0(FULL0 + s * 8); }
        if (rank == 0 && tid == 0) {
            mbar_wait(FULL0 + s * 8, fph[s]); fph[s] ^= 1;
            const uint32_t st = sbase + 1024 + s * STAGE;
            uint64_t ahi = mk_desc(st + A_HI), alo = mk_desc(st + A_LO);
#pragma unroll
            for (int h = 0; h < 2; h++) {
                uint64_t bhi = mk_desc(st + B_HI + h * 16384);
                uint64_t blo = mk_desc(st + B_LO + h * 16384);
                uint32_t dh = tmem + h * 256;
#pragma unroll
                for (int kk = 0; kk < 4; kk++) {
                    // FIX R8->R9: first MMA into EACH TMEM half (i==0,kk==0) must
                    // have en=0 to initialize that half's accumulator region.
                    uint32_t en = ((i > 0) || (kk > 0)) ? 1u : 0u;
                    mma_cg2(dh, ahi + kk * 2, bhi + kk * 2, en);
                    mma_cg2(dh, alo + kk * 2, bhi + kk * 2, 1u);
                    mma_cg2(dh, ahi + kk * 2, blo + kk * 2, 1u);
                }
            }
            asm volatile("tcgen05.commit.cta_group::2.mbarrier::arrive::one.shared::cluster.multicast::cluster.b64 [%0], %1;"
                         :: "r"(MMAB0 + s * 8), "h"((uint16_t)3) : "memory");
        }
        const int j = i + 1;
        if (j < NCH) {
            const int s2 = j & (NST - 1);
            if (j >= NST) { mbar_wait(MMAB0 + s2 * 8, mph[s2]); mph[s2] ^= 1; }
            fill(j);
        }
    }
    mbar_wait(MMAB0 + SLAST * 8, FINPAR);
    asm volatile("tcgen05.fence::after_thread_sync;" ::: "memory");

    // epilogue: warp w -> rows (w&3)*32+lane, col half (w>>2)*256 of the 512-wide tile
    {
        const int gm = m_tile * 256 + (int)rank * 128 + (wid & 3) * 32 + lane;
        float* crow = Cg + (size_t)gm * DOUT + n_tile * 512 + (wid >> 2) * 256;
        const uint32_t cb0 = tmem + (uint32_t)((wid >> 2) * 256);
#pragma unroll
        for (int cb = 0; cb < 256; cb += 32) {
            uint32_t d[32];
            asm volatile("tcgen05.ld.sync.aligned.32x32b.x32.b32 "
                "{%0,%1,%2,%3,%4,%5,%6,%7,%8,%9,%10,%11,%12,%13,%14,%15,"
                "%16,%17,%18,%19,%20,%21,%22,%23,%24,%25,%26,%27,%28,%29,%30,%31}, [%32];"
                : "=r"(d[0]),"=r"(d[1]),"=r"(d[2]),"=r"(d[3]),"=r"(d[4]),"=r"(d[5]),"=r"(d[6]),"=r"(d[7]),
                  "=r"(d[8]),"=r"(d[9]),"=r"(d[10]),"=r"(d[11]),"=r"(d[12]),"=r"(d[13]),"=r"(d[14]),"=r"(d[15]),
                  "=r"(d[16]),"=r"(d[17]),"=r"(d[18]),"=r"(d[19]),"=r"(d[20]),"=r"(d[21]),"=r"(d[22]),"=r"(d[23]),
                  "=r"(d[24]),"=r"(d[25]),"=r"(d[26]),"=r"(d[27]),"=r"(d[28]),"=r"(d[29]),"=r"(d[30]),"=r"(d[31])
                : "r"(cb0 + cb));
            asm volatile("tcgen05.wait::ld.sync.aligned;" ::: "memory");
#pragma unroll
            for (int c = 0; c < 32; c += 4)
                *reinterpret_cast<float4*>(crow + cb + c) =
                    make_float4(__uint_as_float(d[c]), __uint_as_float(d[c+1]),
                                __uint_as_float(d[c+2]), __uint_as_float(d[c+3]));
        }
    }
    __syncthreads();
    if (tid == 0) {
        for (int s = 0; s < NST; s++) { mbar_inval(FULL0 + s * 8); mbar_inval(MMAB0 + s * 8); }
    }
    __syncthreads();
    if (wid == 0) {
        asm volatile("tcgen05.relinquish_alloc_permit.cta_group::2.sync.aligned;");
        asm volatile("tcgen05.dealloc.cta_group::2.sync.aligned.b32 %0, %1;" :: "r"(tmem), "r"(512));
    }
    cluster_sync();
#endif
}

// ---------------------------------------------------------------- launch
// Inputs (metadata order): x, W, b, Wq, Wk, A, Bm
extern "C" void kernel_launch(void* const* d_in, const int* in_sizes, int n_in,
                              void* d_out, int out_size) {
    const float* x  = (const float*)d_in[0];
    const float* W  = (const float*)d_in[1];
    const float* b  = (const float*)d_in[2];
    const float* Wq = (const float*)d_in[3];
    const float* Wk = (const float*)d_in[4];
    const float* A  = (const float*)d_in[5];
    const float* Bm = (const float*)d_in[6];
    float* out = (float*)d_out;

    constexpr int SMEM0 = 1024 + 4 * 32768;    // 132096
    constexpr int SMEM1 = 1024 + 2 * 98304;    // 197632
    cudaFuncSetAttribute(gemm_proj_kernel, cudaFuncAttributeMaxDynamicSharedMemorySize, SMEM0);
    cudaFuncSetAttribute(gemm_main_kernel, cudaFuncAttributeMaxDynamicSharedMemorySize, SMEM1);

    split_x_kernel   <<<(int)(((size_t)MTOK * DIN / 4 + 255) / 256), 256>>>(x);
    split_w_kernel   <<<(int)(((size_t)DOUT * DIN / 4 + 255) / 256), 256>>>(W);
    split_proj_kernel<<<(int)(((size_t)NPROJ_PAD * DIN / 4 + 255) / 256), 256>>>(Wq, Wk, A);
    pack_b2_kernel   <<<(DOUT * GEXT + 255) / 256, 256>>>(Bm, b);

    // projections P = x_hi @ [Wq;Wk;A]_hi^T  (single-panel bf16, K=4096)
    gemm_proj_kernel<<<dim3(2 * (NPROJ_PAD / 256), MTOK / 256), 256, SMEM0>>>();

    // routing -> G ext cols of Xp ([hi|lo] panels)
    routing_kernel<<<(MTOK * 32) / 256, 256>>>();

    // out = x @ W^T + G @ B2^T (+bias): dedup 3-product split GEMM, TN=512/pair
    gemm_main_kernel<<<dim3(2 * (DOUT / 512), MTOK / 256), 256, SMEM1>>>(out);
}